// round 8
// baseline (speedup 1.0000x reference)
#include <cuda_runtime.h>
#include <cstdint>
#include <math.h>

#define S_LEN   512
#define D_HEAD  64
#define BHC     128
#define NV      3

// ---------------------------------------------------------------------------
// Threefry-2x32, key (0,42), partitionable fold out0^out1 (bit-exact R2..R7)
// ---------------------------------------------------------------------------
#define TF_R(r) do { x0 += x1; x1 = __funnelshift_l(x1, x1, (r)); x1 ^= x0; } while (0)

__device__ __forceinline__ uint32_t threefry_word(uint32_t c1) {
    const uint32_t ks1 = 42u;
    const uint32_t ks2 = 0x1BD11BDAu ^ 42u;
    uint32_t x0 = 0u;
    uint32_t x1 = c1 + ks1;
    TF_R(13); TF_R(15); TF_R(26); TF_R(6);
    x0 += ks1; x1 += ks2 + 1u;
    TF_R(17); TF_R(29); TF_R(16); TF_R(24);
    x0 += ks2; x1 += 0u + 2u;
    TF_R(13); TF_R(15); TF_R(26); TF_R(6);
    x0 += 0u; x1 += ks1 + 3u;
    TF_R(17); TF_R(29); TF_R(16); TF_R(24);
    x0 += ks1; x1 += ks2 + 4u;
    TF_R(13); TF_R(15); TF_R(26); TF_R(6);
    x0 += ks2; x1 += 0u + 5u;
    return x0 ^ x1;
}
#define KEEP(bits) ((bits) < 0xA6666600u)   // == uniform(bits) < 0.65f, exact

// ---------------------------------------------------------------------------
// mma.sync helpers (sm_80-level PTX, legal on compute_103)
// ---------------------------------------------------------------------------
__device__ __forceinline__ uint32_t smem_u32(const void* p) {
    uint32_t a;
    asm("{ .reg .u64 t; cvta.to.shared.u64 t, %1; cvt.u32.u64 %0, t; }" : "=r"(a) : "l"(p));
    return a;
}
__device__ __forceinline__ float rna_tf32(float x) {
    uint32_t u;
    asm("cvt.rna.tf32.f32 %0, %1;" : "=r"(u) : "f"(x));
    return __uint_as_float(u);
}

#define LDSM4(r0, r1, r2, r3, addr)                                          \
    asm volatile("ldmatrix.sync.aligned.m8n8.x4.shared.b16 {%0,%1,%2,%3}, [%4];" \
        : "=r"(r0), "=r"(r1), "=r"(r2), "=r"(r3) : "r"(addr))

#define MMA8(c, a, b0, b1)                                                   \
    asm volatile("mma.sync.aligned.m16n8k8.row.col.f32.tf32.tf32.f32 "       \
        "{%0,%1,%2,%3}, {%4,%5,%6,%7}, {%8,%9}, {%0,%1,%2,%3};"              \
        : "+f"((c)[0]), "+f"((c)[1]), "+f"((c)[2]), "+f"((c)[3])             \
        : "r"((a)[0]), "r"((a)[1]), "r"((a)[2]), "r"((a)[3]),                \
          "r"(b0), "r"(b1))

// SMEM layout (float offsets), row stride 68 floats. Total 87296 bytes.
#define LD   68
#define KHI  0                 // 64 x 68
#define KLO  4352
#define VT   8704              // 192 x 68 (all 3 V planes)
#define SM_FLOATS (8704 + 13056)

__global__ void __launch_bounds__(128, 2)
attn_mma(const float* __restrict__ t0, const float* __restrict__ t1,
         const float* __restrict__ t2, const float* __restrict__ t3,
         float* __restrict__ out) {
    extern __shared__ float smf[];
    const uint32_t sb = smem_u32(smf);
    const int tid = threadIdx.x, wid = tid >> 5, lane = tid & 31;
    const int g = lane >> 2, i4 = lane & 3;
    const int bh = blockIdx.x >> 3, q0 = (blockIdx.x & 7) << 6;
    const int qb = wid << 4;                   // warp owns rows [qb, qb+16)
    const float scale = *t3;

    const int ar = lane & 15, ac = (lane >> 4) << 2;   // ldmatrix A pattern
    const int br = lane & 7,  bc = (lane >> 3) << 2;   // ldmatrix B pattern

    const uint32_t rowbase = (uint32_t)(bh * S_LEN + q0);

    const float* Qg = t0 + ((size_t)bh * S_LEN + q0) * D_HEAD;
    const float* Kg = t1 + (size_t)bh * S_LEN * D_HEAD;
    const float* Vg = t2 + (size_t)bh * NV * S_LEN * D_HEAD;

    // ---- prologue: stage Q hi/lo through K buffers, hoist frags to regs ----
#pragma unroll
    for (int i = 0; i < 8; i++) {
        int idx = tid + (i << 7);              // 1024 float4 = 64x64
        int r = idx >> 4, d4 = (idx & 15) << 2;
        float4 x = *(const float4*)(Qg + r * D_HEAD + d4);
        float4 h, l;
        h.x = rna_tf32(x.x); l.x = rna_tf32(x.x - h.x);
        h.y = rna_tf32(x.y); l.y = rna_tf32(x.y - h.y);
        h.z = rna_tf32(x.z); l.z = rna_tf32(x.z - h.z);
        h.w = rna_tf32(x.w); l.w = rna_tf32(x.w - h.w);
        *(float4*)(smf + KHI + r * LD + d4) = h;
        *(float4*)(smf + KLO + r * LD + d4) = l;
    }
    __syncthreads();
    uint32_t qa[8][4], ql[8][4];
#pragma unroll
    for (int ks = 0; ks < 8; ks++) {
        uint32_t off = (uint32_t)((qb + ar) * LD + ks * 8 + ac);
        LDSM4(qa[ks][0], qa[ks][1], qa[ks][2], qa[ks][3], sb + ((KHI + off) << 2));
        LDSM4(ql[ks][0], ql[ks][1], ql[ks][2], ql[ks][3], sb + ((KLO + off) << 2));
    }
    __syncthreads();

    auto loadK = [&](int kt) {
#pragma unroll
        for (int i = 0; i < 8; i++) {
            int idx = tid + (i << 7);
            int r = idx >> 4, d4 = (idx & 15) << 2;
            float4 x = *(const float4*)(Kg + (size_t)(kt * 64 + r) * D_HEAD + d4);
            float4 h, l;
            h.x = rna_tf32(x.x); l.x = rna_tf32(x.x - h.x);
            h.y = rna_tf32(x.y); l.y = rna_tf32(x.y - h.y);
            h.z = rna_tf32(x.z); l.z = rna_tf32(x.z - h.z);
            h.w = rna_tf32(x.w); l.w = rna_tf32(x.w - h.w);
            *(float4*)(smf + KHI + r * LD + d4) = h;
            *(float4*)(smf + KLO + r * LD + d4) = l;
        }
    };
    auto loadV = [&](int kt) {     // VT[dglobal 0..191][k 0..63], all 3 planes
#pragma unroll
        for (int i = 0; i < 24; i++) {
            int c = tid + (i << 7);            // 3072 chunks: 16 kgroups x 192 d
            int kg = c / 192, d = c - kg * 192;
            int v = d >> 6, dl = d & 63;
            const float* p = Vg + (((size_t)v * S_LEN) + kt * 64 + kg * 4) * D_HEAD + dl;
            float4 w;
            w.x = rna_tf32(p[0]);
            w.y = rna_tf32(p[64]);
            w.z = rna_tf32(p[128]);
            w.w = rna_tf32(p[192]);
            *(float4*)(smf + VT + d * LD + kg * 4) = w;
        }
    };

    loadK(0);
    loadV(0);
    __syncthreads();

    float o[24][4];
#pragma unroll
    for (int a = 0; a < 24; a++)
#pragma unroll
        for (int c = 0; c < 4; c++) o[a][c] = 0.0f;
    float rsum0 = 0.0f, rsum1 = 0.0f;

    const int srcL = (lane & 28) | (i4 >> 1);   // quad lane holding col i4 (as c0/c1 pair)
    const int srcH = srcL + 2;                  // quad lane holding col i4+4
    const bool oddc = (i4 & 1) != 0;

    for (int kt = 0; kt < 8; kt++) {
        // ============ MMA1: S[64,64] warp-rows 16 x full k 64 ==============
        float s[8][4];
#pragma unroll
        for (int b = 0; b < 8; b++)
#pragma unroll
            for (int c = 0; c < 4; c++) s[b][c] = 0.0f;

#pragma unroll
        for (int kp = 0; kp < 4; kp++) {
#pragma unroll
            for (int nt = 0; nt < 8; nt++) {
                uint32_t bh4[4], bl4[4];
                uint32_t off = (uint32_t)((8 * nt + br) * LD + kp * 16 + bc);
                LDSM4(bh4[0], bh4[1], bh4[2], bh4[3], sb + ((KHI + off) << 2));
                LDSM4(bl4[0], bl4[1], bl4[2], bl4[3], sb + ((KLO + off) << 2));
#pragma unroll
                for (int sub = 0; sub < 2; sub++) {
                    int ks = kp * 2 + sub;
                    MMA8(s[nt], qa[ks], bh4[2 * sub], bh4[2 * sub + 1]);
                    MMA8(s[nt], ql[ks], bh4[2 * sub], bh4[2 * sub + 1]);
                    MMA8(s[nt], qa[ks], bl4[2 * sub], bl4[2 * sub + 1]);
                }
            }
        }

        // ==== softmax + fused threefry dropout + c-frag -> a-frag shuffle ====
        uint32_t pa[8][4];
        const uint32_t cb0 = (rowbase + (uint32_t)(qb + g)) * 512u
                           + (uint32_t)(kt * 64 + 2 * i4);
        const uint32_t cb1 = cb0 + 8u * 512u;
#pragma unroll
        for (int nt = 0; nt < 8; nt++) {
            float e0 = __expf(s[nt][0] * scale);
            float e1 = __expf(s[nt][1] * scale);
            float e2 = __expf(s[nt][2] * scale);
            float e3 = __expf(s[nt][3] * scale);
            rsum0 += e0 + e1;
            rsum1 += e2 + e3;
            uint32_t c0 = cb0 + (uint32_t)(8 * nt);
            uint32_t c1 = cb1 + (uint32_t)(8 * nt);
            float pc0 = rna_tf32(KEEP(threefry_word(c0))      ? e0 : 0.0f);
            float pc1 = rna_tf32(KEEP(threefry_word(c0 + 1u)) ? e1 : 0.0f);
            float pc2 = rna_tf32(KEEP(threefry_word(c1))      ? e2 : 0.0f);
            float pc3 = rna_tf32(KEEP(threefry_word(c1 + 1u)) ? e3 : 0.0f);
            // c-frag (cols 2*i4, 2*i4+1) -> a-frag (cols i4, i4+4), rows g/g+8
            float t00 = __shfl_sync(0xffffffffu, pc0, srcL);
            float t01 = __shfl_sync(0xffffffffu, pc1, srcL);
            float t10 = __shfl_sync(0xffffffffu, pc2, srcL);
            float t11 = __shfl_sync(0xffffffffu, pc3, srcL);
            float t20 = __shfl_sync(0xffffffffu, pc0, srcH);
            float t21 = __shfl_sync(0xffffffffu, pc1, srcH);
            float t30 = __shfl_sync(0xffffffffu, pc2, srcH);
            float t31 = __shfl_sync(0xffffffffu, pc3, srcH);
            pa[nt][0] = __float_as_uint(oddc ? t01 : t00);
            pa[nt][1] = __float_as_uint(oddc ? t11 : t10);
            pa[nt][2] = __float_as_uint(oddc ? t21 : t20);
            pa[nt][3] = __float_as_uint(oddc ? t31 : t30);
        }

        // ============ MMA2: O[16 rows x 192 cols] += P V (A in regs) =======
#pragma unroll
        for (int kp = 0; kp < 4; kp++) {
#pragma unroll
            for (int nt = 0; nt < 24; nt++) {
                uint32_t bv[4];
                uint32_t off = (uint32_t)((8 * nt + br) * LD + kp * 16 + bc);
                LDSM4(bv[0], bv[1], bv[2], bv[3], sb + ((VT + off) << 2));
                MMA8(o[nt], pa[kp * 2 + 0], bv[0], bv[1]);
                MMA8(o[nt], pa[kp * 2 + 1], bv[2], bv[3]);
            }
        }

        __syncthreads();            // K/V readers done
        if (kt < 7) {
            loadK(kt + 1);
            loadV(kt + 1);
        }
        __syncthreads();            // K/V(kt+1) visible
    }

    // ---- row sums: quad xor-reduce leaves total in all 4 lanes ----
    rsum0 += __shfl_xor_sync(0xffffffffu, rsum0, 1);
    rsum0 += __shfl_xor_sync(0xffffffffu, rsum0, 2);
    rsum1 += __shfl_xor_sync(0xffffffffu, rsum1, 1);
    rsum1 += __shfl_xor_sync(0xffffffffu, rsum1, 2);
    const float inv0 = 1.0f / (rsum0 * 0.65f);
    const float inv1 = 1.0f / (rsum1 * 0.65f);

    // ---- epilogue: normalize + store ----
#pragma unroll
    for (int nt = 0; nt < 24; nt++) {
        int col = 8 * nt + 2 * i4;
        int v = col >> 6, d = col & 63;
        size_t base = (((size_t)bh * NV + v) * S_LEN + q0 + qb + g) * D_HEAD + d;
        float2 w0, w1;
        w0.x = o[nt][0] * inv0;
        w0.y = o[nt][1] * inv0;
        w1.x = o[nt][2] * inv1;
        w1.y = o[nt][3] * inv1;
        *(float2*)(out + base) = w0;
        *(float2*)(out + base + 8 * D_HEAD) = w1;
    }
}

// ---------------------------------------------------------------------------
extern "C" void kernel_launch(void* const* d_in, const int* in_sizes, int n_in,
                              void* d_out, int out_size) {
    const float* t0 = (const float*)d_in[0];
    const float* t1 = (const float*)d_in[1];
    const float* t2 = (const float*)d_in[2];
    const float* t3 = (const float*)d_in[3];
    float* out = (float*)d_out;

    static bool attr_set = false;
    if (!attr_set) {
        cudaFuncSetAttribute(attn_mma, cudaFuncAttributeMaxDynamicSharedMemorySize,
                             SM_FLOATS * (int)sizeof(float));
        attr_set = true;
    }

    attn_mma<<<BHC * 8, 128, SM_FLOATS * sizeof(float)>>>(t0, t1, t2, t3, out);
}

// round 12
// speedup vs baseline: 1.1013x; 1.1013x over previous
#include <cuda_runtime.h>
#include <cstdint>
#include <math.h>

// Problem shape
#define S_LEN   512
#define D_HEAD  64
#define BHC     128
#define NV      3

// ---------------------------------------------------------------------------
// Threefry-2x32, key (0,42), partitionable fold out0^out1 (bit-exact R2..R8)
// ---------------------------------------------------------------------------
#define TF_R(r) do { x0 += x1; x1 = __funnelshift_l(x1, x1, (r)); x1 ^= x0; } while (0)

__device__ __forceinline__ uint32_t threefry_word(uint32_t c1) {
    const uint32_t ks1 = 42u;
    const uint32_t ks2 = 0x1BD11BDAu ^ 42u;
    uint32_t x0 = 0u;
    uint32_t x1 = c1 + ks1;
    TF_R(13); TF_R(15); TF_R(26); TF_R(6);
    x0 += ks1; x1 += ks2 + 1u;
    TF_R(17); TF_R(29); TF_R(16); TF_R(24);
    x0 += ks2; x1 += 0u + 2u;
    TF_R(13); TF_R(15); TF_R(26); TF_R(6);
    x0 += 0u; x1 += ks1 + 3u;
    TF_R(17); TF_R(29); TF_R(16); TF_R(24);
    x0 += ks1; x1 += ks2 + 4u;
    TF_R(13); TF_R(15); TF_R(26); TF_R(6);
    x0 += ks2; x1 += 0u + 5u;
    return x0 ^ x1;
}
// keep <=> uniform(bits) < 0.65f <=> bits < 0xA6666600 (exact integer form)
#define KEEP(bits) ((bits) < 0xA6666600u)

// ---------------------------------------------------------------------------
// mma.sync helpers (sm_80-level PTX, legal on compute_103)
// ---------------------------------------------------------------------------
__device__ __forceinline__ uint32_t smem_u32(const void* p) {
    uint32_t a;
    asm("{ .reg .u64 t; cvta.to.shared.u64 t, %1; cvt.u32.u64 %0, t; }" : "=r"(a) : "l"(p));
    return a;
}
__device__ __forceinline__ float rna_tf32(float x) {
    uint32_t u;
    asm("cvt.rna.tf32.f32 %0, %1;" : "=r"(u) : "f"(x));
    return __uint_as_float(u);
}

#define LDSM4(r0, r1, r2, r3, addr)                                          \
    asm volatile("ldmatrix.sync.aligned.m8n8.x4.shared.b16 {%0,%1,%2,%3}, [%4];" \
        : "=r"(r0), "=r"(r1), "=r"(r2), "=r"(r3) : "r"(addr))

#define MMA8(c, a, b0, b1)                                                   \
    asm volatile("mma.sync.aligned.m16n8k8.row.col.f32.tf32.tf32.f32 "       \
        "{%0,%1,%2,%3}, {%4,%5,%6,%7}, {%8,%9}, {%0,%1,%2,%3};"              \
        : "+f"((c)[0]), "+f"((c)[1]), "+f"((c)[2]), "+f"((c)[3])             \
        : "r"((a)[0]), "r"((a)[1]), "r"((a)[2]), "r"((a)[3]),                \
          "r"(b0), "r"(b1))

// SMEM layout (float offsets), row stride 68 floats. Total 104704 bytes.
#define LD   68
#define QHI  0
#define QLO  4352
#define KHI  8704
#define KLO  13056
#define VT   17408
#define PS   21760
#define RS   26112
#define SM_FLOATS 26176

__global__ void __launch_bounds__(256, 2)
attn_mma(const float* __restrict__ t0, const float* __restrict__ t1,
         const float* __restrict__ t2, const float* __restrict__ t3,
         float* __restrict__ out) {
    extern __shared__ float smf[];
    const uint32_t sb = smem_u32(smf);
    const int tid = threadIdx.x, wid = tid >> 5, lane = tid & 31;
    const int g = lane >> 2, i4 = lane & 3;
    const int bh = blockIdx.x >> 3, q0 = (blockIdx.x & 7) << 6;
    const float scale = *t3;

    // warp tile (both GEMMs): 16 q-rows x 32 cols
    const int qb1 = (wid >> 1) << 4, kb1 = (wid & 1) << 5;

    const int ar = lane & 15, ac = (lane >> 4) << 2;   // ldmatrix A pattern
    const int br = lane & 7,  bc = (lane >> 3) << 2;   // ldmatrix B pattern

    const uint32_t rowbase = (uint32_t)(bh * S_LEN + q0);

    if (tid < 64) smf[RS + tid] = 0.0f;

    // ---- Q [64,64] -> hi/lo ----
    const float* Qg = t0 + ((size_t)bh * S_LEN + q0) * D_HEAD;
#pragma unroll
    for (int i = 0; i < 4; i++) {
        int idx = tid + (i << 8);
        int r = idx >> 4, d4 = (idx & 15) << 2;
        float4 x = *(const float4*)(Qg + r * D_HEAD + d4);
        float4 h, l;
        h.x = rna_tf32(x.x); l.x = rna_tf32(x.x - h.x);
        h.y = rna_tf32(x.y); l.y = rna_tf32(x.y - h.y);
        h.z = rna_tf32(x.z); l.z = rna_tf32(x.z - h.z);
        h.w = rna_tf32(x.w); l.w = rna_tf32(x.w - h.w);
        *(float4*)(smf + QHI + r * LD + d4) = h;
        *(float4*)(smf + QLO + r * LD + d4) = l;
    }

    const float* Kg = t1 + (size_t)bh * S_LEN * D_HEAD;
    const float* Vg = t2 + (size_t)bh * NV * S_LEN * D_HEAD;

    // Fused K tile load (ld+st immediately; no register staging across MMA)
    auto loadK = [&](int kt) {
#pragma unroll
        for (int i = 0; i < 4; i++) {
            int idx = tid + (i << 8);
            int r = idx >> 4, d4 = (idx & 15) << 2;
            float4 x = *(const float4*)(Kg + (size_t)(kt * 64 + r) * D_HEAD + d4);
            float4 h, l;
            h.x = rna_tf32(x.x); l.x = rna_tf32(x.x - h.x);
            h.y = rna_tf32(x.y); l.y = rna_tf32(x.y - h.y);
            h.z = rna_tf32(x.z); l.z = rna_tf32(x.z - h.z);
            h.w = rna_tf32(x.w); l.w = rna_tf32(x.w - h.w);
            *(float4*)(smf + KHI + r * LD + d4) = h;
            *(float4*)(smf + KLO + r * LD + d4) = l;
        }
    };
    // V chunk (kt, v): VT[d][k] transposed, 64x64. 4 float4 per thread.
    auto ldV = [&](int kt, int v, float4* vr) {
#pragma unroll
        for (int i = 0; i < 4; i++) {
            int c = tid + (i << 8);
            int d = c & 63, kg = c >> 6;
            const float* p = Vg + (((size_t)v * S_LEN) + kt * 64 + kg * 4) * D_HEAD + d;
            float4 w;
            w.x = rna_tf32(p[0]);
            w.y = rna_tf32(p[64]);
            w.z = rna_tf32(p[128]);
            w.w = rna_tf32(p[192]);
            vr[i] = w;
        }
    };
    auto stV = [&](const float4* vr) {
#pragma unroll
        for (int i = 0; i < 4; i++) {
            int c = tid + (i << 8);
            int d = c & 63, kg = c >> 6;
            *(float4*)(smf + VT + d * LD + kg * 4) = vr[i];
        }
    };

    {   // prologue: K(0), V(0,0)
        loadK(0);
        float4 vr[4];
        ldV(0, 0, vr);
        stV(vr);
    }
    __syncthreads();

    float o[NV][4][4];
#pragma unroll
    for (int a = 0; a < NV; a++)
#pragma unroll
        for (int b = 0; b < 4; b++)
#pragma unroll
            for (int c = 0; c < 4; c++) o[a][b][c] = 0.0f;
    float rs2[2] = {0.0f, 0.0f};

    // MMA2 helper: O_v += P * V_v  (V in VT)
    auto mma2 = [&](float (*ov)[4]) {
#pragma unroll
        for (int kp = 0; kp < 4; kp++) {
            uint32_t bv[4][4];
#pragma unroll
            for (int nt = 0; nt < 4; nt++) {
                uint32_t rowoff = (uint32_t)((kb1 + 8 * nt + br) * LD + kp * 16 + bc);
                LDSM4(bv[nt][0], bv[nt][1], bv[nt][2], bv[nt][3], sb + ((VT + rowoff) << 2));
            }
#pragma unroll
            for (int sub = 0; sub < 2; sub++) {
                int ks = kp * 2 + sub;
                uint32_t ap[4];
                uint32_t rowoff = (uint32_t)((qb1 + ar) * LD + ks * 8 + ac);
                LDSM4(ap[0], ap[1], ap[2], ap[3], sb + ((PS + rowoff) << 2));
#pragma unroll
                for (int nt = 0; nt < 4; nt++)
                    MMA8(ov[nt], ap, bv[nt][2 * sub], bv[nt][2 * sub + 1]);
            }
        }
    };

    for (int kt = 0; kt < 8; kt++) {
        // ============ MMA1: S[64,64] = Q K^T (3x tf32 split) ==============
        float s[4][4];
#pragma unroll
        for (int b = 0; b < 4; b++)
#pragma unroll
            for (int c = 0; c < 4; c++) s[b][c] = 0.0f;

#pragma unroll
        for (int kp = 0; kp < 4; kp++) {
            uint32_t bhi[4][4], blo[4][4];
#pragma unroll
            for (int nt = 0; nt < 4; nt++) {
                uint32_t rowoff = (uint32_t)((kb1 + 8 * nt + br) * LD + kp * 16 + bc);
                LDSM4(bhi[nt][0], bhi[nt][1], bhi[nt][2], bhi[nt][3], sb + ((KHI + rowoff) << 2));
                LDSM4(blo[nt][0], blo[nt][1], blo[nt][2], blo[nt][3], sb + ((KLO + rowoff) << 2));
            }
#pragma unroll
            for (int sub = 0; sub < 2; sub++) {
                int ks = kp * 2 + sub;
                uint32_t ah[4], al[4];
                uint32_t rowoff = (uint32_t)((qb1 + ar) * LD + ks * 8 + ac);
                LDSM4(ah[0], ah[1], ah[2], ah[3], sb + ((QHI + rowoff) << 2));
                LDSM4(al[0], al[1], al[2], al[3], sb + ((QLO + rowoff) << 2));
#pragma unroll
                for (int nt = 0; nt < 4; nt++) {
                    MMA8(s[nt], ah, bhi[nt][2 * sub], bhi[nt][2 * sub + 1]);
                    MMA8(s[nt], al, bhi[nt][2 * sub], bhi[nt][2 * sub + 1]);
                    MMA8(s[nt], ah, blo[nt][2 * sub], blo[nt][2 * sub + 1]);
                }
            }
        }

        // ============ softmax + fused threefry dropout -> P ===============
#pragma unroll
        for (int dr = 0; dr < 2; dr++) {
            int row = qb1 + 8 * dr + g;
            uint32_t gidx = (rowbase + (uint32_t)row) * 512u + (uint32_t)(kt * 64 + kb1);
            float psum = 0.0f;
#pragma unroll
            for (int nt = 0; nt < 4; nt++) {
                uint32_t c0 = gidx + (uint32_t)(8 * nt + 2 * i4);
                float e0 = __expf(s[nt][dr * 2 + 0] * scale);
                float e1 = __expf(s[nt][dr * 2 + 1] * scale);
                psum += e0 + e1;
                float2 pr;
                pr.x = rna_tf32(KEEP(threefry_word(c0)) ? e0 : 0.0f);
                pr.y = rna_tf32(KEEP(threefry_word(c0 + 1u)) ? e1 : 0.0f);
                *(float2*)(smf + PS + row * LD + kb1 + 8 * nt + 2 * i4) = pr;
            }
            rs2[dr] += psum;
        }
        __syncthreads();   // B1: P visible; K smem free; VT = V(kt,0)

        {
            mma2(o[0]);                        // V(kt,0)
            float4 vr[4];
            ldV(kt, 1, vr);
            __syncthreads();                   // B2: VT reads done
            if (kt < 7) loadK(kt + 1);         // K(kt+1) -> smem (no reg staging)
            stV(vr);                           // VT = V(kt,1)
            __syncthreads();                   // B3
        }

        mma2(o[1]);                            // V(kt,1)
        {
            float4 vr[4];
            ldV(kt, 2, vr);
            __syncthreads();                   // B4
            stV(vr);                           // VT = V(kt,2)
            __syncthreads();                   // B5
        }

        mma2(o[2]);                            // V(kt,2)
        {
            float4 vr[4];
            if (kt < 7) ldV(kt + 1, 0, vr);
            __syncthreads();                   // B6: VT reads done; K(kt+1) visible
            if (kt < 7) stV(vr);               // VT = V(kt+1,0); visible by next B1
        }
    }

    // ---- row-sum reduction (denominator includes dropped elems) ----
#pragma unroll
    for (int dr = 0; dr < 2; dr++) {
        float v = rs2[dr];
        v += __shfl_xor_sync(0xffffffffu, v, 1);
        v += __shfl_xor_sync(0xffffffffu, v, 2);
        if (i4 == 0) atomicAdd(&smf[RS + qb1 + 8 * dr + g], v);
    }
    __syncthreads();
    if (tid < 64) smf[RS + tid] = 1.0f / (smf[RS + tid] * 0.65f);
    __syncthreads();

    // ---- epilogue: normalize + store ----
#pragma unroll
    for (int dr = 0; dr < 2; dr++) {
        int row = qb1 + 8 * dr + g;
        float inv = smf[RS + row];
#pragma unroll
        for (int v = 0; v < NV; v++)
#pragma unroll
            for (int nt = 0; nt < 4; nt++) {
                int col = kb1 + 8 * nt + 2 * i4;
                float2 w;
                w.x = o[v][nt][dr * 2 + 0] * inv;
                w.y = o[v][nt][dr * 2 + 1] * inv;
                *(float2*)(out + (((size_t)bh * NV + v) * S_LEN + q0 + row) * D_HEAD + col) = w;
            }
    }
}

// ---------------------------------------------------------------------------
extern "C" void kernel_launch(void* const* d_in, const int* in_sizes, int n_in,
                              void* d_out, int out_size) {
    const float* t0 = (const float*)d_in[0];
    const float* t1 = (const float*)d_in[1];
    const float* t2 = (const float*)d_in[2];
    const float* t3 = (const float*)d_in[3];
    float* out = (float*)d_out;

    static bool attr_set = false;
    if (!attr_set) {
        cudaFuncSetAttribute(attn_mma, cudaFuncAttributeMaxDynamicSharedMemorySize,
                             SM_FLOATS * (int)sizeof(float));
        attr_set = true;
    }

    attn_mma<<<BHC * 8, 256, SM_FLOATS * sizeof(float)>>>(t0, t1, t2, t3, out);
}

// round 13
// speedup vs baseline: 1.4179x; 1.2875x over previous
#include <cuda_runtime.h>
#include <cuda_fp16.h>
#include <cstdint>
#include <math.h>

// Problem shape
#define S_LEN   512
#define D_HEAD  64
#define BHC     128
#define NV      3

// ---------------------------------------------------------------------------
// Threefry-2x32, key (0,42), partitionable fold out0^out1 (bit-exact R2..R12)
// ---------------------------------------------------------------------------
#define TF_R(r) do { x0 += x1; x1 = __funnelshift_l(x1, x1, (r)); x1 ^= x0; } while (0)

__device__ __forceinline__ uint32_t threefry_word(uint32_t c1) {
    const uint32_t ks1 = 42u;
    const uint32_t ks2 = 0x1BD11BDAu ^ 42u;
    uint32_t x0 = 0u;
    uint32_t x1 = c1 + ks1;
    TF_R(13); TF_R(15); TF_R(26); TF_R(6);
    x0 += ks1; x1 += ks2 + 1u;
    TF_R(17); TF_R(29); TF_R(16); TF_R(24);
    x0 += ks2; x1 += 0u + 2u;
    TF_R(13); TF_R(15); TF_R(26); TF_R(6);
    x0 += 0u; x1 += ks1 + 3u;
    TF_R(17); TF_R(29); TF_R(16); TF_R(24);
    x0 += ks1; x1 += ks2 + 4u;
    TF_R(13); TF_R(15); TF_R(26); TF_R(6);
    x0 += ks2; x1 += 0u + 5u;
    return x0 ^ x1;
}
// keep <=> uniform(bits) < 0.65f <=> bits < 0xA6666600 (exact integer form)
#define KEEP(bits) ((bits) < 0xA6666600u)

// ---------------------------------------------------------------------------
// mma.sync helpers (sm_80-level PTX, legal on compute_103)
// ---------------------------------------------------------------------------
__device__ __forceinline__ uint32_t smem_u32(const void* p) {
    uint32_t a;
    asm("{ .reg .u64 t; cvta.to.shared.u64 t, %1; cvt.u32.u64 %0, t; }" : "=r"(a) : "l"(p));
    return a;
}
__device__ __forceinline__ float rna_tf32(float x) {
    uint32_t u;
    asm("cvt.rna.tf32.f32 %0, %1;" : "=r"(u) : "f"(x));
    return __uint_as_float(u);
}

#define LDSM4(r0, r1, r2, r3, addr)                                          \
    asm volatile("ldmatrix.sync.aligned.m8n8.x4.shared.b16 {%0,%1,%2,%3}, [%4];" \
        : "=r"(r0), "=r"(r1), "=r"(r2), "=r"(r3) : "r"(addr))

// tf32 k8 (MMA2, unchanged from R12)
#define MMA8(c, a, b0, b1)                                                   \
    asm volatile("mma.sync.aligned.m16n8k8.row.col.f32.tf32.tf32.f32 "       \
        "{%0,%1,%2,%3}, {%4,%5,%6,%7}, {%8,%9}, {%0,%1,%2,%3};"              \
        : "+f"((c)[0]), "+f"((c)[1]), "+f"((c)[2]), "+f"((c)[3])             \
        : "r"((a)[0]), "r"((a)[1]), "r"((a)[2]), "r"((a)[3]),                \
          "r"(b0), "r"(b1))

// fp16 k16 (MMA1)
#define MMA16(c, a, b0, b1)                                                  \
    asm volatile("mma.sync.aligned.m16n8k16.row.col.f32.f16.f16.f32 "        \
        "{%0,%1,%2,%3}, {%4,%5,%6,%7}, {%8,%9}, {%0,%1,%2,%3};"              \
        : "+f"((c)[0]), "+f"((c)[1]), "+f"((c)[2]), "+f"((c)[3])             \
        : "r"((a)[0]), "r"((a)[1]), "r"((a)[2]), "r"((a)[3]),                \
          "r"(b0), "r"(b1))

// ---------------------------------------------------------------------------
// SMEM layout (byte offsets). fp16 Q/K tiles: 64 rows x 72 fp16 (144B rows).
// float V/P/RS regions: LD=68 float row stride. Total 106752 bytes.
// ---------------------------------------------------------------------------
#define LDH_B  144                 // fp16 row stride in bytes
#define QHI_B  0                   // 64x72 fp16 = 9216 B
#define QLO_B  9216
#define KHI_B  18432
#define KLO_B  27648
#define LD     68
#define VT     9216                // float offset (byte 36864): 192 x 68 floats
#define PS     22272               // float offset (byte 89088): 64 x 68 floats
#define RS     26624               // float offset (byte 106496): 64 floats
#define SM_BYTES 106752

__global__ void __launch_bounds__(256, 2)
attn_mma(const float* __restrict__ t0, const float* __restrict__ t1,
         const float* __restrict__ t2, const float* __restrict__ t3,
         float* __restrict__ out) {
    extern __shared__ char smc[];
    float* smf = (float*)smc;
    const uint32_t sb = smem_u32(smc);
    const int tid = threadIdx.x, wid = tid >> 5, lane = tid & 31;
    const int g = lane >> 2, i4 = lane & 3;
    const int bh = blockIdx.x >> 3, q0 = (blockIdx.x & 7) << 6;
    const float scale = *t3;

    // warp tile (both GEMMs): 16 q-rows x 32 cols  (R12, proven)
    const int qb1 = (wid >> 1) << 4, kb1 = (wid & 1) << 5;

    // fp16 ldmatrix patterns
    const int ar16 = lane & 15, a8 = (lane >> 4) << 3;                 // A 16x16
    const int brow = (lane & 7) | ((lane >> 4) << 3);                  // B dual-nt
    const int b8 = ((lane >> 3) & 1) << 3;
    // tf32 ldmatrix patterns (MMA2, unchanged)
    const int ar = lane & 15, ac = (lane >> 4) << 2;
    const int br = lane & 7,  bc = (lane >> 3) << 2;

    const uint32_t rowbase = (uint32_t)(bh * S_LEN + q0);

    if (tid < 64) smf[RS + tid] = 0.0f;

    // ---- Q [64,64] -> fp16 hi/lo ----
    const float* Qg = t0 + ((size_t)bh * S_LEN + q0) * D_HEAD;
#pragma unroll
    for (int i = 0; i < 4; i++) {
        int idx = tid + (i << 8);
        int r = idx >> 4, d4 = (idx & 15) << 2;
        float4 x = *(const float4*)(Qg + r * D_HEAD + d4);
        half h0 = __float2half_rn(x.x), h1 = __float2half_rn(x.y);
        half h2 = __float2half_rn(x.z), h3 = __float2half_rn(x.w);
        half l0 = __float2half_rn(x.x - __half2float(h0));
        half l1 = __float2half_rn(x.y - __half2float(h1));
        half l2 = __float2half_rn(x.z - __half2float(h2));
        half l3 = __float2half_rn(x.w - __half2float(h3));
        char* ph = smc + QHI_B + r * LDH_B + d4 * 2;
        char* pl = smc + QLO_B + r * LDH_B + d4 * 2;
        *(half2*)(ph)     = __halves2half2(h0, h1);
        *(half2*)(ph + 4) = __halves2half2(h2, h3);
        *(half2*)(pl)     = __halves2half2(l0, l1);
        *(half2*)(pl + 4) = __halves2half2(l2, l3);
    }

    const float* Kg = t1 + (size_t)bh * S_LEN * D_HEAD;
    const float* Vg = t2 + (size_t)bh * NV * S_LEN * D_HEAD;

    // K tile -> fp16 hi/lo (fused ld+convert+st; full 64x64 coverage)
    auto loadK = [&](int kt) {
#pragma unroll
        for (int i = 0; i < 4; i++) {
            int idx = tid + (i << 8);
            int r = idx >> 4, d4 = (idx & 15) << 2;
            float4 x = *(const float4*)(Kg + (size_t)(kt * 64 + r) * D_HEAD + d4);
            half h0 = __float2half_rn(x.x), h1 = __float2half_rn(x.y);
            half h2 = __float2half_rn(x.z), h3 = __float2half_rn(x.w);
            half l0 = __float2half_rn(x.x - __half2float(h0));
            half l1 = __float2half_rn(x.y - __half2float(h1));
            half l2 = __float2half_rn(x.z - __half2float(h2));
            half l3 = __float2half_rn(x.w - __half2float(h3));
            char* ph = smc + KHI_B + r * LDH_B + d4 * 2;
            char* pl = smc + KLO_B + r * LDH_B + d4 * 2;
            *(half2*)(ph)     = __halves2half2(h0, h1);
            *(half2*)(ph + 4) = __halves2half2(h2, h3);
            *(half2*)(pl)     = __halves2half2(l0, l1);
            *(half2*)(pl + 4) = __halves2half2(l2, l3);
        }
    };
    // V: all 3 planes, tf32 floats, VT[v*64+d][k] (R12's per-plane pattern x3)
    auto loadV = [&](int kt) {
#pragma unroll
        for (int v = 0; v < NV; v++)
#pragma unroll
            for (int i = 0; i < 4; i++) {
                int c = tid + (i << 8);
                int d = c & 63, kg = c >> 6;
                const float* p = Vg + (((size_t)v * S_LEN) + kt * 64 + kg * 4) * D_HEAD + d;
                float4 w;
                w.x = rna_tf32(p[0]);
                w.y = rna_tf32(p[64]);
                w.z = rna_tf32(p[128]);
                w.w = rna_tf32(p[192]);
                *(float4*)(smf + VT + (v * 64 + d) * LD + kg * 4) = w;
            }
    };

    loadK(0);
    loadV(0);
    __syncthreads();

    float o[NV][4][4];
#pragma unroll
    for (int a = 0; a < NV; a++)
#pragma unroll
        for (int b = 0; b < 4; b++)
#pragma unroll
            for (int c = 0; c < 4; c++) o[a][b][c] = 0.0f;
    float rs2[2] = {0.0f, 0.0f};

    for (int kt = 0; kt < 8; kt++) {
        // ====== MMA1: S[64,64] = Q K^T, fp16 split (hh + lh + hl), k16 =====
        float s[4][4];
#pragma unroll
        for (int b = 0; b < 4; b++)
#pragma unroll
            for (int c = 0; c < 4; c++) s[b][c] = 0.0f;

#pragma unroll
        for (int kk = 0; kk < 4; kk++) {
            uint32_t ah[4], al[4];
            uint32_t aoff = (uint32_t)((qb1 + ar16) * LDH_B + (kk * 16 + a8) * 2);
            LDSM4(ah[0], ah[1], ah[2], ah[3], sb + QHI_B + aoff);
            LDSM4(al[0], al[1], al[2], al[3], sb + QLO_B + aoff);
#pragma unroll
            for (int p = 0; p < 2; p++) {
                uint32_t bhp[4], blp[4];
                uint32_t boff = (uint32_t)((kb1 + p * 16 + brow) * LDH_B + (kk * 16 + b8) * 2);
                LDSM4(bhp[0], bhp[1], bhp[2], bhp[3], sb + KHI_B + boff);
                LDSM4(blp[0], blp[1], blp[2], blp[3], sb + KLO_B + boff);
                MMA16(s[2 * p],     ah, bhp[0], bhp[1]);
                MMA16(s[2 * p],     al, bhp[0], bhp[1]);
                MMA16(s[2 * p],     ah, blp[0], blp[1]);
                MMA16(s[2 * p + 1], ah, bhp[2], bhp[3]);
                MMA16(s[2 * p + 1], al, bhp[2], bhp[3]);
                MMA16(s[2 * p + 1], ah, blp[2], blp[3]);
            }
        }

        // ====== softmax + inline threefry dropout -> P (R12 verbatim) ======
#pragma unroll
        for (int dr = 0; dr < 2; dr++) {
            int row = qb1 + 8 * dr + g;
            uint32_t gidx = (rowbase + (uint32_t)row) * 512u + (uint32_t)(kt * 64 + kb1);
            float psum = 0.0f;
#pragma unroll
            for (int nt = 0; nt < 4; nt++) {
                uint32_t c0 = gidx + (uint32_t)(8 * nt + 2 * i4);
                float e0 = __expf(s[nt][dr * 2 + 0] * scale);
                float e1 = __expf(s[nt][dr * 2 + 1] * scale);
                psum += e0 + e1;
                float2 pr;
                pr.x = rna_tf32(KEEP(threefry_word(c0)) ? e0 : 0.0f);
                pr.y = rna_tf32(KEEP(threefry_word(c0 + 1u)) ? e1 : 0.0f);
                *(float2*)(smf + PS + row * LD + kb1 + 8 * nt + 2 * i4) = pr;
            }
            rs2[dr] += psum;
        }
        __syncthreads();   // B1: P visible; K(kt) reads done

        if (kt < 7) loadK(kt + 1);   // overwrites K; visible after B2

        // ====== MMA2: O_v += P V_v, tf32 (R12 verbatim), all 3 v ===========
#pragma unroll
        for (int v = 0; v < NV; v++) {
#pragma unroll
            for (int kp = 0; kp < 4; kp++) {
                uint32_t bv[4][4];
#pragma unroll
                for (int nt = 0; nt < 4; nt++) {
                    uint32_t rowoff = (uint32_t)((v * 64 + kb1 + 8 * nt + br) * LD + kp * 16 + bc);
                    LDSM4(bv[nt][0], bv[nt][1], bv[nt][2], bv[nt][3],
                          sb + ((VT + rowoff) << 2));
                }
#pragma unroll
                for (int sub = 0; sub < 2; sub++) {
                    int ks = kp * 2 + sub;
                    uint32_t ap[4];
                    uint32_t rowoff = (uint32_t)((qb1 + ar) * LD + ks * 8 + ac);
                    LDSM4(ap[0], ap[1], ap[2], ap[3], sb + ((PS + rowoff) << 2));
#pragma unroll
                    for (int nt = 0; nt < 4; nt++)
                        MMA8(o[v][nt], ap, bv[nt][2 * sub], bv[nt][2 * sub + 1]);
                }
            }
        }
        __syncthreads();   // B2: V(kt)/P reads done; K(kt+1) visible

        if (kt < 7) loadV(kt + 1);   // visible at next MMA2 via next B1
    }

    // ---- row-sum reduction (denominator includes dropped elems) ----
#pragma unroll
    for (int dr = 0; dr < 2; dr++) {
        float v = rs2[dr];
        v += __shfl_xor_sync(0xffffffffu, v, 1);
        v += __shfl_xor_sync(0xffffffffu, v, 2);
        if (i4 == 0) atomicAdd(&smf[RS + qb1 + 8 * dr + g], v);
    }
    __syncthreads();
    if (tid < 64) smf[RS + tid] = 1.0f / (smf[RS + tid] * 0.65f);
    __syncthreads();

    // ---- epilogue: normalize + store (R12 verbatim) ----
#pragma unroll
    for (int dr = 0; dr < 2; dr++) {
        int row = qb1 + 8 * dr + g;
        float inv = smf[RS + row];
#pragma unroll
        for (int v = 0; v < NV; v++)
#pragma unroll
            for (int nt = 0; nt < 4; nt++) {
                int col = kb1 + 8 * nt + 2 * i4;
                float2 w;
                w.x = o[v][nt][dr * 2 + 0] * inv;
                w.y = o[v][nt][dr * 2 + 1] * inv;
                *(float2*)(out + (((size_t)bh * NV + v) * S_LEN + q0 + row) * D_HEAD + col) = w;
            }
    }
}

// ---------------------------------------------------------------------------
extern "C" void kernel_launch(void* const* d_in, const int* in_sizes, int n_in,
                              void* d_out, int out_size) {
    const float* t0 = (const float*)d_in[0];
    const float* t1 = (const float*)d_in[1];
    const float* t2 = (const float*)d_in[2];
    const float* t3 = (const float*)d_in[3];
    float* out = (float*)d_out;

    static bool attr_set = false;
    if (!attr_set) {
        cudaFuncSetAttribute(attn_mma, cudaFuncAttributeMaxDynamicSharedMemorySize,
                             SM_BYTES);
        attr_set = true;
    }

    attn_mma<<<BHC * 8, 256, SM_BYTES>>>(t0, t1, t2, t3, out);
}

// round 17
// speedup vs baseline: 1.7339x; 1.2229x over previous
#include <cuda_runtime.h>
#include <cuda_fp16.h>
#include <cstdint>
#include <math.h>

// Problem shape
#define S_LEN   512
#define D_HEAD  64
#define BHC     128
#define NV      3

// ---------------------------------------------------------------------------
// Threefry-2x32, key (0,42), partitionable fold out0^out1 (bit-exact R2..R13)
// ---------------------------------------------------------------------------
#define TF_R(r) do { x0 += x1; x1 = __funnelshift_l(x1, x1, (r)); x1 ^= x0; } while (0)

__device__ __forceinline__ uint32_t threefry_word(uint32_t c1) {
    const uint32_t ks1 = 42u;
    const uint32_t ks2 = 0x1BD11BDAu ^ 42u;
    uint32_t x0 = 0u;
    uint32_t x1 = c1 + ks1;
    TF_R(13); TF_R(15); TF_R(26); TF_R(6);
    x0 += ks1; x1 += ks2 + 1u;
    TF_R(17); TF_R(29); TF_R(16); TF_R(24);
    x0 += ks2; x1 += 0u + 2u;
    TF_R(13); TF_R(15); TF_R(26); TF_R(6);
    x0 += 0u; x1 += ks1 + 3u;
    TF_R(17); TF_R(29); TF_R(16); TF_R(24);
    x0 += ks1; x1 += ks2 + 4u;
    TF_R(13); TF_R(15); TF_R(26); TF_R(6);
    x0 += ks2; x1 += 0u + 5u;
    return x0 ^ x1;
}
// keep <=> uniform(bits) < 0.65f <=> bits < 0xA6666600 (exact integer form)
#define KEEP(bits) ((bits) < 0xA6666600u)

// ---------------------------------------------------------------------------
// mma.sync helpers (sm_80-level PTX, legal on compute_103)
// ---------------------------------------------------------------------------
__device__ __forceinline__ uint32_t smem_u32(const void* p) {
    uint32_t a;
    asm("{ .reg .u64 t; cvta.to.shared.u64 t, %1; cvt.u32.u64 %0, t; }" : "=r"(a) : "l"(p));
    return a;
}

#define LDSM4(r0, r1, r2, r3, addr)                                          \
    asm volatile("ldmatrix.sync.aligned.m8n8.x4.shared.b16 {%0,%1,%2,%3}, [%4];" \
        : "=r"(r0), "=r"(r1), "=r"(r2), "=r"(r3) : "r"(addr))

// fp16 k16 (both GEMMs)
#define MMA16(c, a, b0, b1)                                                  \
    asm volatile("mma.sync.aligned.m16n8k16.row.col.f32.f16.f16.f32 "        \
        "{%0,%1,%2,%3}, {%4,%5,%6,%7}, {%8,%9}, {%0,%1,%2,%3};"              \
        : "+f"((c)[0]), "+f"((c)[1]), "+f"((c)[2]), "+f"((c)[3])             \
        : "r"((a)[0]), "r"((a)[1]), "r"((a)[2]), "r"((a)[3]),                \
          "r"(b0), "r"(b1))

// ---------------------------------------------------------------------------
// SMEM layout (byte offsets). All tiles fp16, 144-byte row stride (72 fp16).
// ---------------------------------------------------------------------------
#define LDH_B  144
#define QHI_B  0
#define QLO_B  9216
#define KHI_B  18432
#define KLO_B  27648
#define VT_B   36864
#define PS_B   64512
#define RSX_B  73728               // 128 floats: rs per (row, half)
#define MTX_B  74240               // 128 floats: tile-max exchange per (row, half)
#define SM_BYTES 74752

__global__ void __launch_bounds__(256, 2)
attn_mma(const float* __restrict__ t0, const float* __restrict__ t1,
         const float* __restrict__ t2, const float* __restrict__ t3,
         float* __restrict__ out) {
    extern __shared__ char smc[];
    float* smf = (float*)smc;
    const uint32_t sb = smem_u32(smc);
    const int tid = threadIdx.x, wid = tid >> 5, lane = tid & 31;
    const int g = lane >> 2, i4 = lane & 3;
    const int bh = blockIdx.x >> 3, q0 = (blockIdx.x & 7) << 6;
    const float scale = *t3;

    // warp tile (both GEMMs): 16 q-rows x 32 cols
    const int qb1 = (wid >> 1) << 4, kb1 = (wid & 1) << 5;
    const int whalf = wid & 1;     // do NOT shadow the `half` type

    // fp16 ldmatrix patterns (R13, proven)
    const int ar16 = lane & 15, a8 = (lane >> 4) << 3;    // A 16x16
    const int brow = (lane & 7) | ((lane >> 4) << 3);     // B dual-nt
    const int b8 = ((lane >> 3) & 1) << 3;

    const uint32_t rowbase = (uint32_t)(bh * S_LEN + q0);

    // ---- Q [64,64] -> fp16 hi/lo ----
    const float* Qg = t0 + ((size_t)bh * S_LEN + q0) * D_HEAD;
#pragma unroll
    for (int i = 0; i < 4; i++) {
        int idx = tid + (i << 8);
        int r = idx >> 4, d4 = (idx & 15) << 2;
        float4 x = *(const float4*)(Qg + r * D_HEAD + d4);
        __half h0 = __float2half_rn(x.x), h1 = __float2half_rn(x.y);
        __half h2 = __float2half_rn(x.z), h3 = __float2half_rn(x.w);
        __half l0 = __float2half_rn(x.x - __half2float(h0));
        __half l1 = __float2half_rn(x.y - __half2float(h1));
        __half l2 = __float2half_rn(x.z - __half2float(h2));
        __half l3 = __float2half_rn(x.w - __half2float(h3));
        char* ph = smc + QHI_B + r * LDH_B + d4 * 2;
        char* pl = smc + QLO_B + r * LDH_B + d4 * 2;
        *(__half2*)(ph)     = __halves2half2(h0, h1);
        *(__half2*)(ph + 4) = __halves2half2(h2, h3);
        *(__half2*)(pl)     = __halves2half2(l0, l1);
        *(__half2*)(pl + 4) = __halves2half2(l2, l3);
    }

    const float* Kg = t1 + (size_t)bh * S_LEN * D_HEAD;
    const float* Vg = t2 + (size_t)bh * NV * S_LEN * D_HEAD;

    // K tile -> fp16 hi/lo
    auto loadK = [&](int kt) {
#pragma unroll
        for (int i = 0; i < 4; i++) {
            int idx = tid + (i << 8);
            int r = idx >> 4, d4 = (idx & 15) << 2;
            float4 x = *(const float4*)(Kg + (size_t)(kt * 64 + r) * D_HEAD + d4);
            __half h0 = __float2half_rn(x.x), h1 = __float2half_rn(x.y);
            __half h2 = __float2half_rn(x.z), h3 = __float2half_rn(x.w);
            __half l0 = __float2half_rn(x.x - __half2float(h0));
            __half l1 = __float2half_rn(x.y - __half2float(h1));
            __half l2 = __float2half_rn(x.z - __half2float(h2));
            __half l3 = __float2half_rn(x.w - __half2float(h3));
            char* ph = smc + KHI_B + r * LDH_B + d4 * 2;
            char* pl = smc + KLO_B + r * LDH_B + d4 * 2;
            *(__half2*)(ph)     = __halves2half2(h0, h1);
            *(__half2*)(ph + 4) = __halves2half2(h2, h3);
            *(__half2*)(pl)     = __halves2half2(l0, l1);
            *(__half2*)(pl + 4) = __halves2half2(l2, l3);
        }
    };
    // V: all 3 planes, fp16, VT[v*64+d][k]
    auto loadV = [&](int kt) {
#pragma unroll
        for (int v = 0; v < NV; v++)
#pragma unroll
            for (int i = 0; i < 4; i++) {
                int c = tid + (i << 8);
                int d = c & 63, kg = c >> 6;
                const float* p = Vg + (((size_t)v * S_LEN) + kt * 64 + kg * 4) * D_HEAD + d;
                __half w0 = __float2half_rn(p[0]);
                __half w1 = __float2half_rn(p[64]);
                __half w2 = __float2half_rn(p[128]);
                __half w3 = __float2half_rn(p[192]);
                char* pv = smc + VT_B + (v * 64 + d) * LDH_B + kg * 8;
                *(__half2*)(pv)     = __halves2half2(w0, w1);
                *(__half2*)(pv + 4) = __halves2half2(w2, w3);
            }
    };

    loadK(0);
    loadV(0);
    __syncthreads();

    float o[NV][4][4];
#pragma unroll
    for (int a = 0; a < NV; a++)
#pragma unroll
        for (int b = 0; b < 4; b++)
#pragma unroll
            for (int c = 0; c < 4; c++) o[a][b][c] = 0.0f;
    float rs2[2] = {0.0f, 0.0f};
    float mrun[2] = {-1e30f, -1e30f};   // joint running max (consistent across warp pair)

    for (int kt = 0; kt < 8; kt++) {
        // ====== MMA1: S[64,64] = Q K^T, fp16 split (hh + lh + hl), k16 =====
        float s[4][4];
#pragma unroll
        for (int b = 0; b < 4; b++)
#pragma unroll
            for (int c = 0; c < 4; c++) s[b][c] = 0.0f;

#pragma unroll
        for (int kk = 0; kk < 4; kk++) {
            uint32_t ah[4], al[4];
            uint32_t aoff = (uint32_t)((qb1 + ar16) * LDH_B + (kk * 16 + a8) * 2);
            LDSM4(ah[0], ah[1], ah[2], ah[3], sb + QHI_B + aoff);
            LDSM4(al[0], al[1], al[2], al[3], sb + QLO_B + aoff);
#pragma unroll
            for (int p = 0; p < 2; p++) {
                uint32_t bhp[4], blp[4];
                uint32_t boff = (uint32_t)((kb1 + p * 16 + brow) * LDH_B + (kk * 16 + b8) * 2);
                LDSM4(bhp[0], bhp[1], bhp[2], bhp[3], sb + KHI_B + boff);
                LDSM4(blp[0], blp[1], blp[2], blp[3], sb + KLO_B + boff);
                MMA16(s[2 * p],     ah, bhp[0], bhp[1]);
                MMA16(s[2 * p],     al, bhp[0], bhp[1]);
                MMA16(s[2 * p],     ah, blp[0], blp[1]);
                MMA16(s[2 * p + 1], ah, bhp[2], bhp[3]);
                MMA16(s[2 * p + 1], al, bhp[2], bhp[3]);
                MMA16(s[2 * p + 1], ah, blp[2], blp[3]);
            }
        }

        // ====== pass 1: per-half tile maxima -> smem exchange ==============
#pragma unroll
        for (int b = 0; b < 4; b++)
#pragma unroll
            for (int c = 0; c < 4; c++) s[b][c] *= scale;

#pragma unroll
        for (int dr = 0; dr < 2; dr++) {
            int row = qb1 + 8 * dr + g;
            float mt = fmaxf(fmaxf(s[0][2 * dr], s[0][2 * dr + 1]),
                             fmaxf(s[1][2 * dr], s[1][2 * dr + 1]));
            mt = fmaxf(mt, fmaxf(fmaxf(s[2][2 * dr], s[2][2 * dr + 1]),
                                 fmaxf(s[3][2 * dr], s[3][2 * dr + 1])));
            mt = fmaxf(mt, __shfl_xor_sync(0xffffffffu, mt, 1));
            mt = fmaxf(mt, __shfl_xor_sync(0xffffffffu, mt, 2));
            if (i4 == 0) smf[(MTX_B >> 2) + row * 2 + whalf] = mt;
        }
        __syncthreads();   // BM: tile maxima visible to warp pair

        // ====== pass 2: joint max -> softmax + threefry dropout -> P =======
#pragma unroll
        for (int dr = 0; dr < 2; dr++) {
            int row = qb1 + 8 * dr + g;
            float mtj = fmaxf(smf[(MTX_B >> 2) + row * 2 + 0],
                              smf[(MTX_B >> 2) + row * 2 + 1]);
            float mnew = fmaxf(mrun[dr], mtj);
            float corr = __expf(mrun[dr] - mnew);
            mrun[dr] = mnew;

            uint32_t gidx = (rowbase + (uint32_t)row) * 512u + (uint32_t)(kt * 64 + kb1);
            float psum = 0.0f;
#pragma unroll
            for (int nt = 0; nt < 4; nt++) {
                uint32_t c0 = gidx + (uint32_t)(8 * nt + 2 * i4);
                float e0 = __expf(s[nt][dr * 2 + 0] - mnew);
                float e1 = __expf(s[nt][dr * 2 + 1] - mnew);
                psum += e0 + e1;
                __half p0 = __float2half_rn(KEEP(threefry_word(c0)) ? e0 : 0.0f);
                __half p1 = __float2half_rn(KEEP(threefry_word(c0 + 1u)) ? e1 : 0.0f);
                *(__half2*)(smc + PS_B + row * LDH_B + (kb1 + 8 * nt + 2 * i4) * 2)
                    = __halves2half2(p0, p1);
            }
            psum += __shfl_xor_sync(0xffffffffu, psum, 1);
            psum += __shfl_xor_sync(0xffffffffu, psum, 2);
            rs2[dr] = rs2[dr] * corr + psum;
#pragma unroll
            for (int v = 0; v < NV; v++)
#pragma unroll
                for (int nt = 0; nt < 4; nt++) {
                    o[v][nt][dr * 2 + 0] *= corr;
                    o[v][nt][dr * 2 + 1] *= corr;
                }
        }
        __syncthreads();   // B1: P visible; K(kt) reads done

        if (kt < 7) loadK(kt + 1);   // visible after B2

        // ====== MMA2: O_v += P V_v, fp16 k16 (ap hoisted across v) =========
#pragma unroll
        for (int kk = 0; kk < 4; kk++) {
            uint32_t ap[4];
            uint32_t aoff = (uint32_t)((qb1 + ar16) * LDH_B + (kk * 16 + a8) * 2);
            LDSM4(ap[0], ap[1], ap[2], ap[3], sb + PS_B + aoff);
#pragma unroll
            for (int v = 0; v < NV; v++) {
#pragma unroll
                for (int p = 0; p < 2; p++) {
                    uint32_t bv[4];
                    uint32_t boff = (uint32_t)((v * 64 + kb1 + p * 16 + brow) * LDH_B
                                               + (kk * 16 + b8) * 2);
                    LDSM4(bv[0], bv[1], bv[2], bv[3], sb + VT_B + boff);
                    MMA16(o[v][2 * p],     ap, bv[0], bv[1]);
                    MMA16(o[v][2 * p + 1], ap, bv[2], bv[3]);
                }
            }
        }
        __syncthreads();   // B2: V(kt)/P reads done; K(kt+1) visible

        if (kt < 7) loadV(kt + 1);   // visible at next MMA2 via next B1
    }

    // ---- publish per-(row, half) rs; same mrun across the pair -> S = sum ----
    if (i4 == 0) {
#pragma unroll
        for (int dr = 0; dr < 2; dr++) {
            int row = qb1 + 8 * dr + g;
            smf[(RSX_B >> 2) + row * 2 + whalf] = rs2[dr];
        }
    }
    __syncthreads();

    // ---- epilogue: normalize + store ----
#pragma unroll
    for (int dr = 0; dr < 2; dr++) {
        int row = qb1 + 8 * dr + g;
        float S = smf[(RSX_B >> 2) + row * 2 + 0] + smf[(RSX_B >> 2) + row * 2 + 1];
        float inv = 1.0f / (S * 0.65f);
#pragma unroll
        for (int v = 0; v < NV; v++)
#pragma unroll
            for (int nt = 0; nt < 4; nt++) {
                int col = kb1 + 8 * nt + 2 * i4;
                float2 w;
                w.x = o[v][nt][dr * 2 + 0] * inv;
                w.y = o[v][nt][dr * 2 + 1] * inv;
                *(float2*)(out + (((size_t)bh * NV + v) * S_LEN + q0 + row) * D_HEAD + col) = w;
            }
    }
}

// ---------------------------------------------------------------------------
extern "C" void kernel_launch(void* const* d_in, const int* in_sizes, int n_in,
                              void* d_out, int out_size) {
    const float* t0 = (const float*)d_in[0];
    const float* t1 = (const float*)d_in[1];
    const float* t2 = (const float*)d_in[2];
    const float* t3 = (const float*)d_in[3];
    float* out = (float*)d_out;

    static bool attr_set = false;
    if (!attr_set) {
        cudaFuncSetAttribute(attn_mma, cudaFuncAttributeMaxDynamicSharedMemorySize,
                             SM_BYTES);
        attr_set = true;
    }

    attn_mma<<<BHC * 8, 256, SM_BYTES>>>(t0, t1, t2, t3, out);
}